// round 13
// baseline (speedup 1.0000x reference)
#include <cuda_runtime.h>
#include <cuda_fp16.h>
#include <math.h>
#include <stdint.h>

#define HH    16
#define NROWS 65536
#define NBL   4096

__device__ float g_wsum[12 * 128];
__device__ float g_hidpart[NBL * 128];   // hidden @ W1[0:1024] + b1

// ---- packed fp32x2 helpers (pre_kernel) ----
__device__ __forceinline__ void ffma2(unsigned long long& d,
                                      unsigned long long a,
                                      unsigned long long b) {
    asm("fma.rn.f32x2 %0, %1, %2, %0;" : "+l"(d) : "l"(a), "l"(b));
}
__device__ __forceinline__ unsigned long long addf32x2(unsigned long long a,
                                                       unsigned long long b) {
    unsigned long long r;
    asm("add.rn.f32x2 %0, %1, %2;" : "=l"(r) : "l"(a), "l"(b));
    return r;
}
__device__ __forceinline__ unsigned long long pack2s(float x) {
    unsigned long long r;
    asm("mov.b64 %0, {%1, %1};" : "=l"(r) : "f"(x));
    return r;
}

// ---- fp16 mma ----
__device__ __forceinline__ void mma_fp16(float* d, const unsigned int* a,
                                         unsigned int b0, unsigned int b1) {
    asm("mma.sync.aligned.m16n8k16.row.col.f32.f16.f16.f32 "
        "{%0,%1,%2,%3}, {%4,%5,%6,%7}, {%8,%9}, {%0,%1,%2,%3};"
        : "+f"(d[0]), "+f"(d[1]), "+f"(d[2]), "+f"(d[3])
        : "r"(a[0]), "r"(a[1]), "r"(a[2]), "r"(a[3]), "r"(b0), "r"(b1));
}

// ============================================================================
// Pre-kernel (unchanged): hidden GEMM + wsum
// ============================================================================
#define PRE_A_HALF (32 * 68)
#define PRE_B_HALF (64 * 64)
#define PRE_SMEM_FLOATS (2 * PRE_A_HALF + 2 * PRE_B_HALF)

__global__ __launch_bounds__(256) void pre_kernel(
    const float* __restrict__ hidden,
    const float* __restrict__ W1,
    const float* __restrict__ b1)
{
    if (blockIdx.x >= 256) {
        int ps = blockIdx.x - 256;
        if (threadIdx.x < 128) {
            int j = threadIdx.x;
            int base = 1024 + ps * 64;
            float s = 0.f;
#pragma unroll
            for (int d = 0; d < 64; d++) s += W1[(base + d) * 128 + j];
            g_wsum[ps * 128 + j] = s;
        }
        return;
    }

    extern __shared__ float sm[];
    float* As = sm;
    float* Bs = sm + 2 * PRE_A_HALF;
    float* pbuf = sm;

    int tid = threadIdx.x;
    int l = tid & 31, w = tid >> 5;
    int kh = w >> 1, wr = w & 1;
    int rowg = l >> 3, colg = l & 7;

    unsigned long long acc[4][2][2];
#pragma unroll
    for (int j = 0; j < 4; j++)
#pragma unroll
        for (int q = 0; q < 2; q++) { acc[j][q][0] = 0ull; acc[j][q][1] = 0ull; }

    int m0 = (blockIdx.x >> 1) * 32;
    int c0 = (blockIdx.x & 1) * 64;

    for (int t = 0; t < 8; t++) {
        __syncthreads();
#pragma unroll
        for (int h = 0; h < 2; h++) {
            int kbase = t * 128 + h * 64;
#pragma unroll
            for (int it = 0; it < 2; it++) {
                int idx = tid + it * 256;
                int r = idx >> 4, k4 = (idx & 15) * 4;
                *(float4*)&As[h * PRE_A_HALF + r * 68 + k4] =
                    *(const float4*)&hidden[(size_t)(m0 + r) * 1024 + kbase + k4];
            }
#pragma unroll
            for (int it = 0; it < 4; it++) {
                int idx = tid + it * 256;
                int k = idx >> 4, c4 = (idx & 15) * 4;
                *(float4*)&Bs[h * PRE_B_HALF + k * 64 + c4] =
                    *(const float4*)&W1[(size_t)(kbase + k) * 128 + c0 + c4];
            }
        }
        __syncthreads();
        int half = kh >> 1, sub = kh & 1;
        const float* Ah = &As[half * PRE_A_HALF + (wr * 16 + rowg) * 68 + sub * 32];
        const float* Bh = &Bs[half * PRE_B_HALF + sub * 32 * 64 + colg * 4];
#pragma unroll 4
        for (int kk = 0; kk < 32; kk++) {
            ulonglong2 w0 = *(const ulonglong2*)(Bh + kk * 64);
            ulonglong2 w1 = *(const ulonglong2*)(Bh + kk * 64 + 32);
#pragma unroll
            for (int j = 0; j < 4; j++) {
                unsigned long long xd = pack2s(Ah[j * 4 * 68 + kk]);
                ffma2(acc[j][0][0], xd, w0.x); ffma2(acc[j][0][1], xd, w0.y);
                ffma2(acc[j][1][0], xd, w1.x); ffma2(acc[j][1][1], xd, w1.y);
            }
        }
    }
    __syncthreads();
    if (kh & 1) {
        int part = kh >> 1;
#pragma unroll
        for (int j = 0; j < 4; j++) {
            int r = wr * 16 + rowg + 4 * j;
#pragma unroll
            for (int q = 0; q < 2; q++)
#pragma unroll
                for (int p = 0; p < 2; p++)
                    *(unsigned long long*)&pbuf[part * 2176 + r * 68 + colg * 4 + q * 32 + 2 * p] =
                        acc[j][q][p];
        }
    }
    __syncthreads();
    if (!(kh & 1)) {
        int part = kh >> 1;
#pragma unroll
        for (int j = 0; j < 4; j++) {
            int r = wr * 16 + rowg + 4 * j;
#pragma unroll
            for (int q = 0; q < 2; q++)
#pragma unroll
                for (int p = 0; p < 2; p++) {
                    unsigned long long* a =
                        (unsigned long long*)&pbuf[part * 2176 + r * 68 + colg * 4 + q * 32 + 2 * p];
                    *a = addf32x2(*a, acc[j][q][p]);
                }
        }
    }
    __syncthreads();
#pragma unroll
    for (int it = 0; it < 2; it++) {
        int idx = tid + it * 256;
        int r = idx >> 4, c4 = (idx & 15) * 4;
        float4 h0 = *(const float4*)&pbuf[r * 68 + c4];
        float4 h1 = *(const float4*)&pbuf[2176 + r * 68 + c4];
        float4 bv = *(const float4*)&b1[c0 + c4];
        float4 o = make_float4(h0.x + h1.x + bv.x, h0.y + h1.y + bv.y,
                               h0.z + h1.z + bv.z, h0.w + h1.w + bv.w);
        *(float4*)&g_hidpart[(size_t)(m0 + r) * 128 + c0 + c4] = o;
    }
}

// ============================================================================
// Main kernel: fp16 MMA, stats as 17th k-step. TM=64 rows/tile (1024 tiles),
// 2 CTAs/SM (grid 296). 16 warps = rw(4: 16-row) x cw(4: 32-col), warp m16xn32.
// Smem/CTA ~105 KB; __launch_bounds__(512,2) caps regs at 64.
// ============================================================================
#define WFA_OFF  0              // [4 cw][17 kt][32 lane][4 words]  (nt 0,1)
#define WFB_OFF  8704           // same (nt 2,3)
#define X2_OFF   17408          // x half2: [64][140] words; HB fp32 aliases
#define X2_PITCH 140
#define W2T_OFF  26368          // w2T: [4][132]
#define SM_FLOATS 26896         // 107584 B

__global__ __launch_bounds__(512, 2) void main_kernel(
    const float* __restrict__ br0, const float* __restrict__ br1,
    const float* __restrict__ br2, const float* __restrict__ br3,
    const float* __restrict__ W1, const float* __restrict__ W2,
    const float* __restrict__ b2, const float* __restrict__ eps_floor,
    const float* __restrict__ temp, float* __restrict__ out)
{
    extern __shared__ float S[];
    unsigned int* US = (unsigned int*)S;
    int tid = threadIdx.x;
    int l = tid & 31, w = tid >> 5;
    int rw = w >> 2, cw = w & 3;

    // ---- one-time: W rows 1792.. -> fp16 B-fragments (ksteps 0..15) ----
    for (int i = tid; i < 128 * 128; i += 512) {
        int k2 = i >> 7, n = i & 127;
        int k = 2 * k2;
        __half2 hv = __floats2half2_rn(W1[(size_t)(1792 + k) * 128 + n],
                                       W1[(size_t)(1793 + k) * 128 + n]);
        int kt = k2 >> 3, kk = k2 & 7;
        int b = kk >> 2, lk = kk & 3;
        int cwi = n >> 5, nn = n & 31;
        int nt = nn >> 3, lhi = nn & 7;
        int lane = lhi * 4 + lk;
        int base = (nt >> 1) ? WFB_OFF : WFA_OFF;
        int widx = (nt & 1) * 2 + b;
        US[base + ((cwi * 17 + kt) * 32 + lane) * 4 + widx] = *(unsigned int*)&hv;
    }
    // ---- one-time: wsum -> B-fragments for kstep 16 (ps 0..11, pads 0) ----
    for (int i = tid; i < 8 * 128; i += 512) {
        int kk = i >> 7, n = i & 127;
        int ps0 = 2 * kk, ps1 = ps0 + 1;
        float v0 = (ps0 < 12) ? g_wsum[ps0 * 128 + n] : 0.f;
        float v1 = (ps1 < 12) ? g_wsum[ps1 * 128 + n] : 0.f;
        __half2 hv = __floats2half2_rn(v0, v1);
        int b = kk >> 2, lk = kk & 3;
        int cwi = n >> 5, nn = n & 31;
        int nt = nn >> 3, lhi = nn & 7;
        int lane = lhi * 4 + lk;
        int base = (nt >> 1) ? WFB_OFF : WFA_OFF;
        int widx = (nt & 1) * 2 + b;
        US[base + ((cwi * 17 + 16) * 32 + lane) * 4 + widx] = *(unsigned int*)&hv;
    }
    { int c = tid >> 2, n = tid & 3; S[W2T_OFF + n * 132 + c] = W2[c * 4 + n]; }

    const int ntiles = NROWS / 64;   // 1024
    for (int tile = blockIdx.x; tile < ntiles; tile += gridDim.x) {
        int rg0 = tile * 64;
        __syncthreads();   // prev epilogue HB reads done; one-time init iter 0

        // ---- x -> half2 smem + stats via 16-lane shuffle reduction ----
#pragma unroll
        for (int p = 0; p < 4; p++) {
            const float* bp = (p == 0) ? br0 : (p == 1) ? br1 : (p == 2) ? br2 : br3;
            const float4* bp4 = (const float4*)bp + (size_t)rg0 * 16;
#pragma unroll
            for (int it = 0; it < 2; it++) {
                int idx = tid + it * 512;
                int r = idx >> 4, d4 = (idx & 15) * 4;
                float4 v = bp4[idx];
                __half2 h0 = __floats2half2_rn(v.x, v.y);
                __half2 h1 = __floats2half2_rn(v.z, v.w);
                *(uint2*)&US[X2_OFF + r * X2_PITCH + p * 32 + (d4 >> 1)] =
                    make_uint2(*(unsigned int*)&h0, *(unsigned int*)&h1);
                float sum = v.x + v.y + v.z + v.w;
                float sq = v.x * v.x + v.y * v.y + v.z * v.z + v.w * v.w;
                float mx = fmaxf(fmaxf(v.x, v.y), fmaxf(v.z, v.w));
#pragma unroll
                for (int off = 1; off < 16; off <<= 1) {
                    sum += __shfl_xor_sync(0xffffffffu, sum, off);
                    sq  += __shfl_xor_sync(0xffffffffu, sq, off);
                    mx = fmaxf(mx, __shfl_xor_sync(0xffffffffu, mx, off));
                }
                int sl = l & 15;
                if (sl == 0) {
                    __half* hrow = (__half*)&US[X2_OFF + r * X2_PITCH];
                    hrow[256 + p * 3 + 0] = __float2half_rn(sum * (1.0f / 64.0f));
                    hrow[256 + p * 3 + 1] =
                        __float2half_rn(sqrtf(fmaxf(sq * (1.0f / 64.0f), 1e-8f)));
                    hrow[256 + p * 3 + 2] = __float2half_rn(mx);
                } else if (p == 0 && sl == 1) {
                    *(uint2*)&US[X2_OFF + r * X2_PITCH + 134] = make_uint2(0u, 0u);
                }
            }
        }
        __syncthreads();

        // ---- fp16 tensor GEMM: warp m16 x n32, k=272 (17 ksteps) ----
        float acc[4][4];
#pragma unroll
        for (int nt = 0; nt < 4; nt++)
#pragma unroll
            for (int i = 0; i < 4; i++) acc[nt][i] = 0.f;
        {
            const unsigned int* xa0 =
                &US[X2_OFF + (rw * 16 + (l >> 2)) * X2_PITCH + (l & 3)];
            const unsigned int* wfa = &US[WFA_OFF + ((cw * 17) * 32 + l) * 4];
            const unsigned int* wfb = &US[WFB_OFF + ((cw * 17) * 32 + l) * 4];
#pragma unroll
            for (int kt = 0; kt < 17; kt++) {
                const unsigned int* xm = xa0 + kt * 8;
                unsigned int a[4];
                a[0] = xm[0];
                a[1] = xm[8 * X2_PITCH];
                a[2] = xm[4];
                a[3] = xm[8 * X2_PITCH + 4];
                uint4 bA = *(const uint4*)&wfa[kt * 128];
                uint4 bB = *(const uint4*)&wfb[kt * 128];
                mma_fp16(acc[0], a, bA.x, bA.y);
                mma_fp16(acc[1], a, bA.z, bA.w);
                mma_fp16(acc[2], a, bB.x, bB.y);
                mma_fp16(acc[3], a, bB.z, bB.w);
            }
        }
        __syncthreads();   // x reads done -> HB may overwrite x region

        // ---- C fragments -> HB (fp32, aliases x region, pitch 140) ----
        {
            float* HBf = &S[X2_OFF];
            int colb = cw * 32 + (l & 3) * 2;
            int row0 = rw * 16 + (l >> 2);
#pragma unroll
            for (int nt = 0; nt < 4; nt++) {
                *(float2*)&HBf[row0 * X2_PITCH + colb + nt * 8] =
                    make_float2(acc[nt][0], acc[nt][1]);
                *(float2*)&HBf[(row0 + 8) * X2_PITCH + colb + nt * 8] =
                    make_float2(acc[nt][2], acc[nt][3]);
            }
        }
        __syncthreads();

        // ---- epilogue: thread = (row r, 16-col chunk) ----
        {
            const float* HBf = &S[X2_OFF];
            int r = tid >> 3;
            int c0 = (tid & 7) * 16;
            int rg = rg0 + r;
            float h[16];
#pragma unroll
            for (int i = 0; i < 4; i++) {
                float4 a = *(const float4*)&HBf[r * X2_PITCH + c0 + 4 * i];
                float4 v = *(const float4*)&g_hidpart[(size_t)(rg >> 4) * 128 + c0 + 4 * i];
                h[4 * i + 0] = a.x + v.x;
                h[4 * i + 1] = a.y + v.y;
                h[4 * i + 2] = a.z + v.z;
                h[4 * i + 3] = a.w + v.w;
            }
            float lp0 = 0.f, lp1 = 0.f, lp2 = 0.f, lp3 = 0.f;
#pragma unroll
            for (int i = 0; i < 4; i++) {
                float g0 = 0.5f * h[4*i+0] * (1.0f + erff(h[4*i+0] * 0.7071067811865476f));
                float g1 = 0.5f * h[4*i+1] * (1.0f + erff(h[4*i+1] * 0.7071067811865476f));
                float g2 = 0.5f * h[4*i+2] * (1.0f + erff(h[4*i+2] * 0.7071067811865476f));
                float g3 = 0.5f * h[4*i+3] * (1.0f + erff(h[4*i+3] * 0.7071067811865476f));
                float4 wa = *(const float4*)&S[W2T_OFF + 0 * 132 + c0 + 4 * i];
                float4 wb = *(const float4*)&S[W2T_OFF + 1 * 132 + c0 + 4 * i];
                float4 wc4 = *(const float4*)&S[W2T_OFF + 2 * 132 + c0 + 4 * i];
                float4 wd = *(const float4*)&S[W2T_OFF + 3 * 132 + c0 + 4 * i];
                lp0 += g0 * wa.x + g1 * wa.y + g2 * wa.z + g3 * wa.w;
                lp1 += g0 * wb.x + g1 * wb.y + g2 * wb.z + g3 * wb.w;
                lp2 += g0 * wc4.x + g1 * wc4.y + g2 * wc4.z + g3 * wc4.w;
                lp3 += g0 * wd.x + g1 * wd.y + g2 * wd.z + g3 * wd.w;
            }
#pragma unroll
            for (int off = 1; off < 8; off <<= 1) {
                lp0 += __shfl_xor_sync(0xffffffffu, lp0, off);
                lp1 += __shfl_xor_sync(0xffffffffu, lp1, off);
                lp2 += __shfl_xor_sync(0xffffffffu, lp2, off);
                lp3 += __shfl_xor_sync(0xffffffffu, lp3, off);
            }
            if ((tid & 7) == 0) {
                int hh = rg & (HH - 1);
                float t = fminf(fmaxf(temp[hh], 0.2f), 10.0f);
                float invt = 1.0f / t;
                float q0 = (lp0 + b2[0]) * invt;
                float q1 = (lp1 + b2[1]) * invt;
                float q2 = (lp2 + b2[2]) * invt;
                float q3 = (lp3 + b2[3]) * invt;
                float m = fmaxf(fmaxf(q0, q1), fmaxf(q2, q3));
                float e0 = expf(q0 - m), e1 = expf(q1 - m);
                float e2 = expf(q2 - m), e3 = expf(q3 - m);
                float inv = 1.0f / (e0 + e1 + e2 + e3);
                float w0 = e0 * inv, w1 = e1 * inv, w2v = e2 * inv, w3 = e3 * inv;
                const float* ef = eps_floor + hh * 4;
                w0 = fmaxf(w0, fminf(fmaxf(ef[0], 1e-7f), 0.1f));
                w1 = fmaxf(w1, fminf(fmaxf(ef[1], 1e-7f), 0.1f));
                w2v = fmaxf(w2v, fminf(fmaxf(ef[2], 1e-7f), 0.1f));
                w3 = fmaxf(w3, fminf(fmaxf(ef[3], 1e-7f), 0.1f));
                float inv2 = 1.0f / (w0 + w1 + w2v + w3);
                *(float4*)&out[(size_t)rg * 4] =
                    make_float4(w0 * inv2, w1 * inv2, w2v * inv2, w3 * inv2);
            }
        }
    }
}

// ============================================================================
// Launch
// ============================================================================
extern "C" void kernel_launch(void* const* d_in, const int* in_sizes, int n_in,
                              void* d_out, int out_size)
{
    const float* hidden = (const float*)d_in[0];
    const float* br0    = (const float*)d_in[1];
    const float* br1    = (const float*)d_in[2];
    const float* br2    = (const float*)d_in[3];
    const float* br3    = (const float*)d_in[4];
    const float* W1     = (const float*)d_in[5];
    const float* b1     = (const float*)d_in[6];
    const float* W2     = (const float*)d_in[7];
    const float* b2     = (const float*)d_in[8];
    const float* eps    = (const float*)d_in[9];
    const float* temp   = (const float*)d_in[10];
    float* out = (float*)d_out;

    cudaFuncSetAttribute(pre_kernel, cudaFuncAttributeMaxDynamicSharedMemorySize,
                         PRE_SMEM_FLOATS * 4);
    cudaFuncSetAttribute(main_kernel, cudaFuncAttributeMaxDynamicSharedMemorySize,
                         SM_FLOATS * 4);

    pre_kernel<<<268, 256, PRE_SMEM_FLOATS * 4>>>(hidden, W1, b1);
    main_kernel<<<296, 512, SM_FLOATS * 4>>>(br0, br1, br2, br3, W1, W2,
                                             b2, eps, temp, out);
}

// round 16
// speedup vs baseline: 1.3707x; 1.3707x over previous
#include <cuda_runtime.h>
#include <cuda_fp16.h>
#include <math.h>
#include <stdint.h>

#define HH    16
#define NROWS 65536
#define NBL   4096

__device__ float g_wsum[12 * 128];
__device__ float g_hidpart[NBL * 128];   // hidden @ W1[0:1024] + b1

// ---- packed fp32x2 helpers (pre_kernel) ----
__device__ __forceinline__ void ffma2(unsigned long long& d,
                                      unsigned long long a,
                                      unsigned long long b) {
    asm("fma.rn.f32x2 %0, %1, %2, %0;" : "+l"(d) : "l"(a), "l"(b));
}
__device__ __forceinline__ unsigned long long addf32x2(unsigned long long a,
                                                       unsigned long long b) {
    unsigned long long r;
    asm("add.rn.f32x2 %0, %1, %2;" : "=l"(r) : "l"(a), "l"(b));
    return r;
}
__device__ __forceinline__ unsigned long long pack2s(float x) {
    unsigned long long r;
    asm("mov.b64 %0, {%1, %1};" : "=l"(r) : "f"(x));
    return r;
}

// ---- fp16 mma ----
__device__ __forceinline__ void mma_fp16(float* d, const unsigned int* a,
                                         unsigned int b0, unsigned int b1) {
    asm("mma.sync.aligned.m16n8k16.row.col.f32.f16.f16.f32 "
        "{%0,%1,%2,%3}, {%4,%5,%6,%7}, {%8,%9}, {%0,%1,%2,%3};"
        : "+f"(d[0]), "+f"(d[1]), "+f"(d[2]), "+f"(d[3])
        : "r"(a[0]), "r"(a[1]), "r"(a[2]), "r"(a[3]), "r"(b0), "r"(b1));
}

// ============================================================================
// Pre-kernel (unchanged): hidden GEMM + wsum
// ============================================================================
#define PRE_A_HALF (32 * 68)
#define PRE_B_HALF (64 * 64)
#define PRE_SMEM_FLOATS (2 * PRE_A_HALF + 2 * PRE_B_HALF)

__global__ __launch_bounds__(256) void pre_kernel(
    const float* __restrict__ hidden,
    const float* __restrict__ W1,
    const float* __restrict__ b1)
{
    if (blockIdx.x >= 256) {
        int ps = blockIdx.x - 256;
        if (threadIdx.x < 128) {
            int j = threadIdx.x;
            int base = 1024 + ps * 64;
            float s = 0.f;
#pragma unroll
            for (int d = 0; d < 64; d++) s += W1[(base + d) * 128 + j];
            g_wsum[ps * 128 + j] = s;
        }
        return;
    }

    extern __shared__ float sm[];
    float* As = sm;
    float* Bs = sm + 2 * PRE_A_HALF;
    float* pbuf = sm;

    int tid = threadIdx.x;
    int l = tid & 31, w = tid >> 5;
    int kh = w >> 1, wr = w & 1;
    int rowg = l >> 3, colg = l & 7;

    unsigned long long acc[4][2][2];
#pragma unroll
    for (int j = 0; j < 4; j++)
#pragma unroll
        for (int q = 0; q < 2; q++) { acc[j][q][0] = 0ull; acc[j][q][1] = 0ull; }

    int m0 = (blockIdx.x >> 1) * 32;
    int c0 = (blockIdx.x & 1) * 64;

    for (int t = 0; t < 8; t++) {
        __syncthreads();
#pragma unroll
        for (int h = 0; h < 2; h++) {
            int kbase = t * 128 + h * 64;
#pragma unroll
            for (int it = 0; it < 2; it++) {
                int idx = tid + it * 256;
                int r = idx >> 4, k4 = (idx & 15) * 4;
                *(float4*)&As[h * PRE_A_HALF + r * 68 + k4] =
                    *(const float4*)&hidden[(size_t)(m0 + r) * 1024 + kbase + k4];
            }
#pragma unroll
            for (int it = 0; it < 4; it++) {
                int idx = tid + it * 256;
                int k = idx >> 4, c4 = (idx & 15) * 4;
                *(float4*)&Bs[h * PRE_B_HALF + k * 64 + c4] =
                    *(const float4*)&W1[(size_t)(kbase + k) * 128 + c0 + c4];
            }
        }
        __syncthreads();
        int half = kh >> 1, sub = kh & 1;
        const float* Ah = &As[half * PRE_A_HALF + (wr * 16 + rowg) * 68 + sub * 32];
        const float* Bh = &Bs[half * PRE_B_HALF + sub * 32 * 64 + colg * 4];
#pragma unroll 4
        for (int kk = 0; kk < 32; kk++) {
            ulonglong2 w0 = *(const ulonglong2*)(Bh + kk * 64);
            ulonglong2 w1 = *(const ulonglong2*)(Bh + kk * 64 + 32);
#pragma unroll
            for (int j = 0; j < 4; j++) {
                unsigned long long xd = pack2s(Ah[j * 4 * 68 + kk]);
                ffma2(acc[j][0][0], xd, w0.x); ffma2(acc[j][0][1], xd, w0.y);
                ffma2(acc[j][1][0], xd, w1.x); ffma2(acc[j][1][1], xd, w1.y);
            }
        }
    }
    __syncthreads();
    if (kh & 1) {
        int part = kh >> 1;
#pragma unroll
        for (int j = 0; j < 4; j++) {
            int r = wr * 16 + rowg + 4 * j;
#pragma unroll
            for (int q = 0; q < 2; q++)
#pragma unroll
                for (int p = 0; p < 2; p++)
                    *(unsigned long long*)&pbuf[part * 2176 + r * 68 + colg * 4 + q * 32 + 2 * p] =
                        acc[j][q][p];
        }
    }
    __syncthreads();
    if (!(kh & 1)) {
        int part = kh >> 1;
#pragma unroll
        for (int j = 0; j < 4; j++) {
            int r = wr * 16 + rowg + 4 * j;
#pragma unroll
            for (int q = 0; q < 2; q++)
#pragma unroll
                for (int p = 0; p < 2; p++) {
                    unsigned long long* a =
                        (unsigned long long*)&pbuf[part * 2176 + r * 68 + colg * 4 + q * 32 + 2 * p];
                    *a = addf32x2(*a, acc[j][q][p]);
                }
        }
    }
    __syncthreads();
#pragma unroll
    for (int it = 0; it < 2; it++) {
        int idx = tid + it * 256;
        int r = idx >> 4, c4 = (idx & 15) * 4;
        float4 h0 = *(const float4*)&pbuf[r * 68 + c4];
        float4 h1 = *(const float4*)&pbuf[2176 + r * 68 + c4];
        float4 bv = *(const float4*)&b1[c0 + c4];
        float4 o = make_float4(h0.x + h1.x + bv.x, h0.y + h1.y + bv.y,
                               h0.z + h1.z + bv.z, h0.w + h1.w + bv.w);
        *(float4*)&g_hidpart[(size_t)(m0 + r) * 128 + c0 + c4] = o;
    }
}

// ============================================================================
// Main kernel: fp16 MMA, stats as 17th k-step, TM=128 (R12 config) with
// DE-ALIASED HB and software-pipelined staging: next tile's LDGs issue
// before the epilogue; cvt/STS/stats run after it. 2 syncs per tile.
// ============================================================================
#define WFA_OFF  0              // [4 cw][17 kt][32 lane][4 words]
#define WFB_OFF  8704
#define X2_OFF   17408          // x half2: [128][140] words
#define X2_PITCH 140
#define HB_OFF   35328          // HB fp32: [128][132]  (separate region!)
#define HB_PITCH 132
#define W2T_OFF  52224          // w2T: [4][132]
#define SM_FLOATS 52752         // 211008 B

__device__ __forceinline__ void stage_loads(
    const float* __restrict__ br0, const float* __restrict__ br1,
    const float* __restrict__ br2, const float* __restrict__ br3,
    int rg0, int tid, float4* pv)
{
#pragma unroll
    for (int p = 0; p < 4; p++) {
        const float* bp = (p == 0) ? br0 : (p == 1) ? br1 : (p == 2) ? br2 : br3;
        const float4* bp4 = (const float4*)bp + (size_t)rg0 * 16;
#pragma unroll
        for (int it = 0; it < 4; it++)
            pv[p * 4 + it] = bp4[tid + it * 512];
    }
}

__device__ __forceinline__ void stage_store(unsigned int* US, int tid, int l,
                                            const float4* pv)
{
#pragma unroll
    for (int p = 0; p < 4; p++) {
#pragma unroll
        for (int it = 0; it < 4; it++) {
            int idx = tid + it * 512;
            int r = idx >> 4, d4 = (idx & 15) * 4;
            float4 v = pv[p * 4 + it];
            __half2 h0 = __floats2half2_rn(v.x, v.y);
            __half2 h1 = __floats2half2_rn(v.z, v.w);
            *(uint2*)&US[X2_OFF + r * X2_PITCH + p * 32 + (d4 >> 1)] =
                make_uint2(*(unsigned int*)&h0, *(unsigned int*)&h1);
            float sum = v.x + v.y + v.z + v.w;
            float sq = v.x * v.x + v.y * v.y + v.z * v.z + v.w * v.w;
            float mx = fmaxf(fmaxf(v.x, v.y), fmaxf(v.z, v.w));
#pragma unroll
            for (int off = 1; off < 16; off <<= 1) {
                sum += __shfl_xor_sync(0xffffffffu, sum, off);
                sq  += __shfl_xor_sync(0xffffffffu, sq, off);
                mx = fmaxf(mx, __shfl_xor_sync(0xffffffffu, mx, off));
            }
            int sl = l & 15;
            if (sl == 0) {
                __half* hrow = (__half*)&US[X2_OFF + r * X2_PITCH];
                hrow[256 + p * 3 + 0] = __float2half_rn(sum * (1.0f / 64.0f));
                hrow[256 + p * 3 + 1] =
                    __float2half_rn(sqrtf(fmaxf(sq * (1.0f / 64.0f), 1e-8f)));
                hrow[256 + p * 3 + 2] = __float2half_rn(mx);
            } else if (p == 0 && sl == 1) {
                *(uint2*)&US[X2_OFF + r * X2_PITCH + 134] = make_uint2(0u, 0u);
            }
        }
    }
}

__global__ __launch_bounds__(512, 1) void main_kernel(
    const float* __restrict__ br0, const float* __restrict__ br1,
    const float* __restrict__ br2, const float* __restrict__ br3,
    const float* __restrict__ W1, const float* __restrict__ W2,
    const float* __restrict__ b2, const float* __restrict__ eps_floor,
    const float* __restrict__ temp, float* __restrict__ out)
{
    extern __shared__ float S[];
    unsigned int* US = (unsigned int*)S;
    int tid = threadIdx.x;
    int l = tid & 31, w = tid >> 5;
    int rw = w >> 2, cw = w & 3;

    // ---- one-time: W rows 1792.. -> fp16 B-fragments (ksteps 0..15) ----
    for (int i = tid; i < 128 * 128; i += 512) {
        int k2 = i >> 7, n = i & 127;
        int k = 2 * k2;
        __half2 hv = __floats2half2_rn(W1[(size_t)(1792 + k) * 128 + n],
                                       W1[(size_t)(1793 + k) * 128 + n]);
        int kt = k2 >> 3, kk = k2 & 7;
        int b = kk >> 2, lk = kk & 3;
        int cwi = n >> 5, nn = n & 31;
        int nt = nn >> 3, lhi = nn & 7;
        int lane = lhi * 4 + lk;
        int base = (nt >> 1) ? WFB_OFF : WFA_OFF;
        int widx = (nt & 1) * 2 + b;
        US[base + ((cwi * 17 + kt) * 32 + lane) * 4 + widx] = *(unsigned int*)&hv;
    }
    // ---- one-time: wsum -> B-fragments for kstep 16 ----
    for (int i = tid; i < 8 * 128; i += 512) {
        int kk = i >> 7, n = i & 127;
        int ps0 = 2 * kk, ps1 = ps0 + 1;
        float v0 = (ps0 < 12) ? g_wsum[ps0 * 128 + n] : 0.f;
        float v1 = (ps1 < 12) ? g_wsum[ps1 * 128 + n] : 0.f;
        __half2 hv = __floats2half2_rn(v0, v1);
        int b = kk >> 2, lk = kk & 3;
        int cwi = n >> 5, nn = n & 31;
        int nt = nn >> 3, lhi = nn & 7;
        int lane = lhi * 4 + lk;
        int base = (nt >> 1) ? WFB_OFF : WFA_OFF;
        int widx = (nt & 1) * 2 + b;
        US[base + ((cwi * 17 + 16) * 32 + lane) * 4 + widx] = *(unsigned int*)&hv;
    }
    { int c = tid >> 2, n = tid & 3; S[W2T_OFF + n * 132 + c] = W2[c * 4 + n]; }

    const int ntiles = NROWS / 128;   // 512

    // ---- prologue: stage first tile ----
    int tile = blockIdx.x;
    if (tile < ntiles) {
        float4 pv[16];
        stage_loads(br0, br1, br2, br3, tile * 128, tid, pv);
        stage_store(US, tid, l, pv);
    }

    for (; tile < ntiles; tile += gridDim.x) {
        int rg0 = tile * 128;
        __syncthreads();   // staging(t) + (iter0) one-time init visible

        // ---- fp16 tensor GEMM: warp m32 x n32, k=272 (17 ksteps) ----
        float acc[2][4][4];
#pragma unroll
        for (int mg = 0; mg < 2; mg++)
#pragma unroll
            for (int nt = 0; nt < 4; nt++)
#pragma unroll
                for (int i = 0; i < 4; i++) acc[mg][nt][i] = 0.f;
        {
            const unsigned int* xa0 =
                &US[X2_OFF + (rw * 32 + (l >> 2)) * X2_PITCH + (l & 3)];
            const unsigned int* wfa = &US[WFA_OFF + ((cw * 17) * 32 + l) * 4];
            const unsigned int* wfb = &US[WFB_OFF + ((cw * 17) * 32 + l) * 4];
#pragma unroll
            for (int kt = 0; kt < 17; kt++) {
                unsigned int a[2][4];
#pragma unroll
                for (int mg = 0; mg < 2; mg++) {
                    const unsigned int* xm = xa0 + mg * 16 * X2_PITCH + kt * 8;
                    a[mg][0] = xm[0];
                    a[mg][1] = xm[8 * X2_PITCH];
                    a[mg][2] = xm[4];
                    a[mg][3] = xm[8 * X2_PITCH + 4];
                }
                uint4 bA = *(const uint4*)&wfa[kt * 128];
                uint4 bB = *(const uint4*)&wfb[kt * 128];
#pragma unroll
                for (int mg = 0; mg < 2; mg++) {
                    mma_fp16(acc[mg][0], a[mg], bA.x, bA.y);
                    mma_fp16(acc[mg][1], a[mg], bA.z, bA.w);
                    mma_fp16(acc[mg][2], a[mg], bB.x, bB.y);
                    mma_fp16(acc[mg][3], a[mg], bB.z, bB.w);
                }
            }
        }

        // ---- C fragments -> HB (separate region: no sync needed vs MMA) ----
        {
            int colb = cw * 32 + (l & 3) * 2;
#pragma unroll
            for (int mg = 0; mg < 2; mg++) {
                int row0 = rw * 32 + mg * 16 + (l >> 2);
#pragma unroll
                for (int nt = 0; nt < 4; nt++) {
                    *(float2*)&S[HB_OFF + row0 * HB_PITCH + colb + nt * 8] =
                        make_float2(acc[mg][nt][0], acc[mg][nt][1]);
                    *(float2*)&S[HB_OFF + (row0 + 8) * HB_PITCH + colb + nt * 8] =
                        make_float2(acc[mg][nt][2], acc[mg][nt][3]);
                }
            }
        }

        // ---- prefetch next tile's gmem loads (drain behind epilogue) ----
        int ntile = tile + gridDim.x;
        bool pf = ntile < ntiles;
        float4 pv[16];
        if (pf) stage_loads(br0, br1, br2, br3, ntile * 128, tid, pv);

        __syncthreads();   // HB visible; all MMA X-reads complete

        // ---- epilogue: 2 passes; thread = (row r, 16-col chunk) ----
#pragma unroll
        for (int e = 0; e < 2; e++) {
            int r = (tid >> 3) + 64 * e;
            int c0 = (tid & 7) * 16;
            int rg = rg0 + r;
            float h[16];
#pragma unroll
            for (int i = 0; i < 4; i++) {
                float4 a = *(const float4*)&S[HB_OFF + r * HB_PITCH + c0 + 4 * i];
                float4 v = *(const float4*)&g_hidpart[(size_t)(rg >> 4) * 128 + c0 + 4 * i];
                h[4 * i + 0] = a.x + v.x;
                h[4 * i + 1] = a.y + v.y;
                h[4 * i + 2] = a.z + v.z;
                h[4 * i + 3] = a.w + v.w;
            }
            float lp0 = 0.f, lp1 = 0.f, lp2 = 0.f, lp3 = 0.f;
#pragma unroll
            for (int i = 0; i < 4; i++) {
                float g0 = 0.5f * h[4*i+0] * (1.0f + erff(h[4*i+0] * 0.7071067811865476f));
                float g1 = 0.5f * h[4*i+1] * (1.0f + erff(h[4*i+1] * 0.7071067811865476f));
                float g2 = 0.5f * h[4*i+2] * (1.0f + erff(h[4*i+2] * 0.7071067811865476f));
                float g3 = 0.5f * h[4*i+3] * (1.0f + erff(h[4*i+3] * 0.7071067811865476f));
                float4 wa = *(const float4*)&S[W2T_OFF + 0 * 132 + c0 + 4 * i];
                float4 wb = *(const float4*)&S[W2T_OFF + 1 * 132 + c0 + 4 * i];
                float4 wc4 = *(const float4*)&S[W2T_OFF + 2 * 132 + c0 + 4 * i];
                float4 wd = *(const float4*)&S[W2T_OFF + 3 * 132 + c0 + 4 * i];
                lp0 += g0 * wa.x + g1 * wa.y + g2 * wa.z + g3 * wa.w;
                lp1 += g0 * wb.x + g1 * wb.y + g2 * wb.z + g3 * wb.w;
                lp2 += g0 * wc4.x + g1 * wc4.y + g2 * wc4.z + g3 * wc4.w;
                lp3 += g0 * wd.x + g1 * wd.y + g2 * wd.z + g3 * wd.w;
            }
#pragma unroll
            for (int off = 1; off < 8; off <<= 1) {
                lp0 += __shfl_xor_sync(0xffffffffu, lp0, off);
                lp1 += __shfl_xor_sync(0xffffffffu, lp1, off);
                lp2 += __shfl_xor_sync(0xffffffffu, lp2, off);
                lp3 += __shfl_xor_sync(0xffffffffu, lp3, off);
            }
            if ((tid & 7) == 0) {
                int hh = rg & (HH - 1);
                float t = fminf(fmaxf(temp[hh], 0.2f), 10.0f);
                float invt = 1.0f / t;
                float q0 = (lp0 + b2[0]) * invt;
                float q1 = (lp1 + b2[1]) * invt;
                float q2 = (lp2 + b2[2]) * invt;
                float q3 = (lp3 + b2[3]) * invt;
                float m = fmaxf(fmaxf(q0, q1), fmaxf(q2, q3));
                float e0 = expf(q0 - m), e1 = expf(q1 - m);
                float e2 = expf(q2 - m), e3 = expf(q3 - m);
                float inv = 1.0f / (e0 + e1 + e2 + e3);
                float w0 = e0 * inv, w1 = e1 * inv, w2v = e2 * inv, w3 = e3 * inv;
                const float* ef = eps_floor + hh * 4;
                w0 = fmaxf(w0, fminf(fmaxf(ef[0], 1e-7f), 0.1f));
                w1 = fmaxf(w1, fminf(fmaxf(ef[1], 1e-7f), 0.1f));
                w2v = fmaxf(w2v, fminf(fmaxf(ef[2], 1e-7f), 0.1f));
                w3 = fmaxf(w3, fminf(fmaxf(ef[3], 1e-7f), 0.1f));
                float inv2 = 1.0f / (w0 + w1 + w2v + w3);
                *(float4*)&out[(size_t)rg * 4] =
                    make_float4(w0 * inv2, w1 * inv2, w2v * inv2, w3 * inv2);
            }
        }

        // ---- store next tile's staged data (loads have drained by now) ----
        if (pf) stage_store(US, tid, l, pv);
    }
}

// ============================================================================
// Launch
// ============================================================================
extern "C" void kernel_launch(void* const* d_in, const int* in_sizes, int n_in,
                              void* d_out, int out_size)
{
    const float* hidden = (const float*)d_in[0];
    const float* br0    = (const float*)d_in[1];
    const float* br1    = (const float*)d_in[2];
    const float* br2    = (const float*)d_in[3];
    const float* br3    = (const float*)d_in[4];
    const float* W1     = (const float*)d_in[5];
    const float* b1     = (const float*)d_in[6];
    const float* W2     = (const float*)d_in[7];
    const float* b2     = (const float*)d_in[8];
    const float* eps    = (const float*)d_in[9];
    const float* temp   = (const float*)d_in[10];
    float* out = (float*)d_out;

    cudaFuncSetAttribute(pre_kernel, cudaFuncAttributeMaxDynamicSharedMemorySize,
                         PRE_SMEM_FLOATS * 4);
    cudaFuncSetAttribute(main_kernel, cudaFuncAttributeMaxDynamicSharedMemorySize,
                         SM_FLOATS * 4);

    pre_kernel<<<268, 256, PRE_SMEM_FLOATS * 4>>>(hidden, W1, b1);
    main_kernel<<<148, 512, SM_FLOATS * 4>>>(br0, br1, br2, br3, W1, W2,
                                             b2, eps, temp, out);
}